// round 15
// baseline (speedup 1.0000x reference)
#include <cuda_runtime.h>
#include <cuda_fp16.h>
#include <cstdint>
#include <math.h>

#define HID   2048
#define MROWS 2048      // b*s = 2*1024
#define SEQ   1024
#define NHEADS 32
#define NKV   8
#define HD    64
#define FFND  8192

// ---------------- scratch (static device arrays; no allocation) ----------------
__device__ float  d_attn   [MROWS * HID];
__device__ float  d_rope   [MROWS * 64];      // per-row cos[32] | sin[32]
__device__ __half d_normed_h [MROWS * HID];
__device__ __half d_q_h      [MROWS * HID];
__device__ __half d_k_h      [MROWS * NKV * HD];
__device__ __half d_v_h      [MROWS * NKV * HD];
__device__ __half d_ctx_h    [MROWS * HID];
__device__ __half d_normed2_h[MROWS * HID];
__device__ __half d_u_h      [MROWS * FFND];
__device__ __half d_g_h      [MROWS * FFND];
// transposed fp16 weights [N, K] (rebuilt every replay; pure function of inputs)
__device__ __half d_wq_t[2048 * 2048];
__device__ __half d_wk_t[512 * 2048];
__device__ __half d_wv_t[512 * 2048];
__device__ __half d_wo_t[2048 * 2048];
__device__ __half d_wg_t[8192 * 2048];
__device__ __half d_wu_t[8192 * 2048];
__device__ __half d_wd_t[2048 * 8192];

// ---------------- merged weight transpose: ONE launch for all 7 weights --------------
// tile counts (32x32 tiles): wq 4096 | wk 1024 | wv 1024 | wo 4096 | wg 16384 | wu 16384 | wd 16384
struct TJob { const float* in; __half* out; int R, C, tilesX, tileBase; };
__global__ void __launch_bounds__(256) transpose_all(
    const float* wq, const float* wk, const float* wv, const float* wo,
    const float* wg, const float* wu, const float* wd,
    __half* wq_t, __half* wk_t, __half* wv_t, __half* wo_t,
    __half* wg_t, __half* wu_t, __half* wd_t)
{
    __shared__ float tile[32][33];
    int bid = blockIdx.x;
    const float* in; __half* out; int R, C, tx0, ty0;
    // prefix offsets: 0,4096,5120,6144,10240,26624,43008,59392
    if (bid < 4096)       { in = wq; out = wq_t; R = 2048; C = 2048; bid -= 0;     }
    else if (bid < 5120)  { in = wk; out = wk_t; R = 2048; C = 512;  bid -= 4096;  }
    else if (bid < 6144)  { in = wv; out = wv_t; R = 2048; C = 512;  bid -= 5120;  }
    else if (bid < 10240) { in = wo; out = wo_t; R = 2048; C = 2048; bid -= 6144;  }
    else if (bid < 26624) { in = wg; out = wg_t; R = 2048; C = 8192; bid -= 10240; }
    else if (bid < 43008) { in = wu; out = wu_t; R = 2048; C = 8192; bid -= 26624; }
    else                  { in = wd; out = wd_t; R = 8192; C = 2048; bid -= 43008; }
    int tilesX = C >> 5;
    tx0 = (bid % tilesX) * 32;
    ty0 = (bid / tilesX) * 32;

    int tx = threadIdx.x & 31, ty = threadIdx.x >> 5;   // 32 x 8
    #pragma unroll
    for (int i = 0; i < 32; i += 8)
        tile[ty + i][tx] = in[(size_t)(ty0 + ty + i) * C + tx0 + tx];
    __syncthreads();
    #pragma unroll
    for (int i = 0; i < 32; i += 8)
        out[(size_t)(tx0 + ty + i) * R + ty0 + tx] = __float2half_rn(tile[tx][ty + i]);
}

// ---------------- RMSNorm (fused optional residual; fp16 output -> GEMM A operand) ---
__global__ void __launch_bounds__(256) rmsnorm_kernel(
    const float* __restrict__ x, const float* __restrict__ res,
    const float* __restrict__ w, __half* __restrict__ out)
{
    int row = blockIdx.x;
    int tid = threadIdx.x;
    const float4* xr = reinterpret_cast<const float4*>(x + (size_t)row * HID);
    float4 v0 = xr[tid];
    float4 v1 = xr[tid + 256];
    if (res) {
        const float4* rr = reinterpret_cast<const float4*>(res + (size_t)row * HID);
        float4 r0 = rr[tid], r1 = rr[tid + 256];
        v0.x += r0.x; v0.y += r0.y; v0.z += r0.z; v0.w += r0.w;
        v1.x += r1.x; v1.y += r1.y; v1.z += r1.z; v1.w += r1.w;
    }
    float ss = v0.x*v0.x + v0.y*v0.y + v0.z*v0.z + v0.w*v0.w
             + v1.x*v1.x + v1.y*v1.y + v1.z*v1.z + v1.w*v1.w;
    #pragma unroll
    for (int o = 16; o; o >>= 1) ss += __shfl_xor_sync(0xffffffffu, ss, o);
    __shared__ float red[8];
    if ((tid & 31) == 0) red[tid >> 5] = ss;
    __syncthreads();
    float tot = red[0] + red[1] + red[2] + red[3] + red[4] + red[5] + red[6] + red[7];
    float sc = rsqrtf(tot / (float)HID + 1e-5f);
    const float4* wr = reinterpret_cast<const float4*>(w);
    float4 w0 = wr[tid], w1 = wr[tid + 256];
    __half2* orow = reinterpret_cast<__half2*>(out + (size_t)row * HID);
    orow[tid * 2]           = __floats2half2_rn(v0.x*sc*w0.x, v0.y*sc*w0.y);
    orow[tid * 2 + 1]       = __floats2half2_rn(v0.z*sc*w0.z, v0.w*sc*w0.w);
    orow[(tid + 256) * 2]   = __floats2half2_rn(v1.x*sc*w1.x, v1.y*sc*w1.y);
    orow[(tid + 256) * 2+1] = __floats2half2_rn(v1.z*sc*w1.z, v1.w*sc*w1.w);
}

// ---------------- fp16 GEMM: CTA 128x128, warp 64x32 (2m x 4n), BK=32, 2-stage -------
// A: half [M,K] row-major. Bt: half [N,K] row-major (pre-transposed weights).
// mode: 0 fp32 C | 1 fp32 C = acc + Add | 3 half C = silu(acc) | 4 half C = acc
__device__ __forceinline__ void gemm_body(
    const __half* __restrict__ A, const __half* __restrict__ Bt,
    float* __restrict__ C, __half* __restrict__ Ch, const float* __restrict__ Add,
    int N, int K, int bm, int bn, int mode)
{
    __shared__ __half As[2][128][40];   // 32 data + 8 pad: stride 20 banks -> conflict-free
    __shared__ __half Bs[2][128][40];

    int tid = threadIdx.x;
    int warp = tid >> 5, lane = tid & 31;
    int wm = (warp >> 2) * 64, wn = (warp & 3) * 32;
    int g = lane >> 2, t = lane & 3;

    int lrow = tid >> 1;                 // 0..127
    int lcb  = (tid & 1) * 16;           // half-chunk base: 0 or 16

    const __half* aSrc = A  + (size_t)(bm + lrow) * K + lcb;
    const __half* bSrc = Bt + (size_t)(bn + lrow) * K + lcb;

    float acc[4][4][4] = {};
    int KT = K >> 5;

    auto issue = [&](int buf) {
        unsigned d0 = (unsigned)__cvta_generic_to_shared(&As[buf][lrow][lcb]);
        asm volatile("cp.async.cg.shared.global [%0], [%1], 16;\n" :: "r"(d0), "l"(aSrc));
        asm volatile("cp.async.cg.shared.global [%0], [%1], 16;\n" :: "r"(d0 + 16), "l"(aSrc + 8));
        unsigned d1 = (unsigned)__cvta_generic_to_shared(&Bs[buf][lrow][lcb]);
        asm volatile("cp.async.cg.shared.global [%0], [%1], 16;\n" :: "r"(d1), "l"(bSrc));
        asm volatile("cp.async.cg.shared.global [%0], [%1], 16;\n" :: "r"(d1 + 16), "l"(bSrc + 8));
        asm volatile("cp.async.commit_group;\n");
        aSrc += 32;
        bSrc += 32;
    };

    issue(0);
    int cur = 0;
    for (int kt = 0; kt < KT; kt++) {
        if (kt + 1 < KT) {
            issue(cur ^ 1);
            asm volatile("cp.async.wait_group 1;\n");
        } else {
            asm volatile("cp.async.wait_group 0;\n");
        }
        __syncthreads();

        #pragma unroll
        for (int ks = 0; ks < 32; ks += 16) {
            uint32_t a[4][4], b[4][2];
            #pragma unroll
            for (int mi = 0; mi < 4; mi++) {
                int r = wm + mi * 16 + g;
                a[mi][0] = *reinterpret_cast<const uint32_t*>(&As[cur][r    ][ks + 2*t]);
                a[mi][1] = *reinterpret_cast<const uint32_t*>(&As[cur][r + 8][ks + 2*t]);
                a[mi][2] = *reinterpret_cast<const uint32_t*>(&As[cur][r    ][ks + 2*t + 8]);
                a[mi][3] = *reinterpret_cast<const uint32_t*>(&As[cur][r + 8][ks + 2*t + 8]);
            }
            #pragma unroll
            for (int ni = 0; ni < 4; ni++) {
                int c = wn + ni * 8 + g;
                b[ni][0] = *reinterpret_cast<const uint32_t*>(&Bs[cur][c][ks + 2*t]);
                b[ni][1] = *reinterpret_cast<const uint32_t*>(&Bs[cur][c][ks + 2*t + 8]);
            }
            #pragma unroll
            for (int mi = 0; mi < 4; mi++)
                #pragma unroll
                for (int ni = 0; ni < 4; ni++) {
                    asm volatile(
                        "mma.sync.aligned.m16n8k16.row.col.f32.f16.f16.f32 "
                        "{%0,%1,%2,%3},{%4,%5,%6,%7},{%8,%9},{%0,%1,%2,%3};"
                        : "+f"(acc[mi][ni][0]), "+f"(acc[mi][ni][1]),
                          "+f"(acc[mi][ni][2]), "+f"(acc[mi][ni][3])
                        : "r"(a[mi][0]), "r"(a[mi][1]), "r"(a[mi][2]), "r"(a[mi][3]),
                          "r"(b[ni][0]), "r"(b[ni][1]));
                }
        }
        __syncthreads();
        cur ^= 1;
    }

    // epilogue
    #pragma unroll
    for (int mi = 0; mi < 4; mi++) {
        #pragma unroll
        for (int ni = 0; ni < 4; ni++) {
            int r0 = bm + wm + mi * 16 + g;
            int c0 = bn + wn + ni * 8 + 2 * t;
            size_t i0 = (size_t)r0 * N + c0;
            size_t i1 = i0 + (size_t)8 * N;
            float2 lo = make_float2(acc[mi][ni][0], acc[mi][ni][1]);
            float2 hi = make_float2(acc[mi][ni][2], acc[mi][ni][3]);
            if (mode == 0) {
                *reinterpret_cast<float2*>(C + i0) = lo;
                *reinterpret_cast<float2*>(C + i1) = hi;
            } else if (mode == 1) {
                const float2 a0 = *reinterpret_cast<const float2*>(Add + i0);
                const float2 a1 = *reinterpret_cast<const float2*>(Add + i1);
                lo.x += a0.x; lo.y += a0.y; hi.x += a1.x; hi.y += a1.y;
                *reinterpret_cast<float2*>(C + i0) = lo;
                *reinterpret_cast<float2*>(C + i1) = hi;
            } else if (mode == 3) {
                *reinterpret_cast<__half2*>(Ch + i0) =
                    __floats2half2_rn(lo.x / (1.f + __expf(-lo.x)), lo.y / (1.f + __expf(-lo.y)));
                *reinterpret_cast<__half2*>(Ch + i1) =
                    __floats2half2_rn(hi.x / (1.f + __expf(-hi.x)), hi.y / (1.f + __expf(-hi.y)));
            } else {  // mode 4
                *reinterpret_cast<__half2*>(Ch + i0) = __floats2half2_rn(lo.x, lo.y);
                *reinterpret_cast<__half2*>(Ch + i1) = __floats2half2_rn(hi.x, hi.y);
            }
        }
    }
}

__global__ void __launch_bounds__(256) gemm_h(
    const __half* __restrict__ A, const __half* __restrict__ Bt,
    float* __restrict__ C, const float* __restrict__ Add,
    int N, int K, int mode)
{
    gemm_body(A, Bt, C, nullptr, Add, N, K, blockIdx.y * 128, blockIdx.x * 128, mode);
}

// fused QKV (+ rope table build): grid (24,16); tiles 0-15 Q, 16-19 K, 20-23 V; fp16 out
__global__ void __launch_bounds__(256) qkv_kernel(
    const __half* __restrict__ A,
    const __half* __restrict__ wq_t, const __half* __restrict__ wk_t, const __half* __restrict__ wv_t,
    __half* __restrict__ q, __half* __restrict__ k, __half* __restrict__ v,
    const int* __restrict__ posids, float* __restrict__ ropetab)
{
    {
        int lb = blockIdx.y * 24 + blockIdx.x;
        for (int e = lb * 256 + threadIdx.x; e < MROWS * 32; e += 384 * 256) {
            int row = e >> 5, i = e & 31;
            double invf = exp2(-(double)i * (18.931568569324174 / 32.0)); // 500000^{-i/32}
            float ang = (float)((double)posids[row] * invf);
            float s, c;
            sincosf(ang, &s, &c);
            ropetab[row * 64 + i]      = c;
            ropetab[row * 64 + 32 + i] = s;
        }
    }
    int nt = blockIdx.x, bm = blockIdx.y * 128;
    const __half* Bt; __half* Cp; int N, bn;
    if (nt < 16)      { Bt = wq_t; Cp = q; N = HID;      bn = nt * 128; }
    else if (nt < 20) { Bt = wk_t; Cp = k; N = NKV * HD; bn = (nt - 16) * 128; }
    else              { Bt = wv_t; Cp = v; N = NKV * HD; bn = (nt - 20) * 128; }
    gemm_body(A, Bt, nullptr, Cp, nullptr, N, HID, bm, bn, 4);
}

// fused up+gate: grid (128,16); tiles 0-63 up (half), 64-127 gate (silu half)
__global__ void __launch_bounds__(256) upgate_kernel(
    const __half* __restrict__ A,
    const __half* __restrict__ wu_t, const __half* __restrict__ wg_t,
    __half* __restrict__ u, __half* __restrict__ g)
{
    int nt = blockIdx.x, bm = blockIdx.y * 128;
    const __half* Bt; __half* Cp; int bn, mode;
    if (nt < 64) { Bt = wu_t; Cp = u; bn = nt * 128;        mode = 4; }
    else         { Bt = wg_t; Cp = g; bn = (nt - 64) * 128; mode = 3; }
    gemm_body(A, Bt, nullptr, Cp, nullptr, FFND, HID, bm, bn, mode);
}

// g = half(gsilu * u)  (in place on g; fp32 math)
__global__ void __launch_bounds__(256) swiglu_mul(
    __half* __restrict__ g, const __half* __restrict__ u, int n2)
{
    int i = blockIdx.x * 256 + threadIdx.x;
    if (i < n2) {
        float2 gv = __half22float2(reinterpret_cast<__half2*>(g)[i]);
        float2 uv = __half22float2(reinterpret_cast<const __half2*>(u)[i]);
        reinterpret_cast<__half2*>(g)[i] = __floats2half2_rn(gv.x * uv.x, gv.y * uv.y);
    }
}

// ---------------- RoPE apply (in place on fp16 q/k; fp32 math) ----------------
__global__ void __launch_bounds__(256) rope_apply(
    __half* __restrict__ q, __half* __restrict__ k, const float* __restrict__ tab)
{
    int id = blockIdx.x * 256 + threadIdx.x;    // MROWS * 40 * 32
    int row = id / (40 * 32);
    int rem = id - row * (40 * 32);
    int head = rem >> 5;
    int i = rem & 31;
    float c = tab[row * 64 + i], s = tab[row * 64 + 32 + i];
    __half* base;
    if (head < NHEADS) base = q + (size_t)row * HID + head * HD;
    else               base = k + (size_t)row * (NKV * HD) + (head - NHEADS) * HD;
    float x1 = __half2float(base[i]), x2 = __half2float(base[i + 32]);
    base[i]      = __float2half_rn(x1 * c - x2 * s);
    base[i + 32] = __float2half_rn(x2 * c + x1 * s);
}

// ---------------- fp16 tensor-core flash attention (causal, GQA) ---------------------
// All operands already fp16 in global. Q scaled by exact 0.125 via __hmul2.
#define APADH 72
#define ATTM_SMEM ((128 + 64 + 128 + 64) * APADH * 2)
__global__ void __launch_bounds__(256) attn_mma(
    const __half* __restrict__ q, const __half* __restrict__ kk,
    const __half* __restrict__ vv, __half* __restrict__ ctx)
{
    extern __shared__ __half smh[];
    __half* Qs = smh;                    // [128][APADH]
    __half* Ks = Qs + 128 * APADH;       // [64][APADH]
    __half* Ps = Ks + 64 * APADH;        // [128][APADH] (warp-private rows)
    __half* Vt = Ps + 128 * APADH;       // [64][APADH]  dim-major, key contiguous

    int qt = 7 - blockIdx.x;
    int bh = blockIdx.y;
    int b = bh >> 5, h = bh & 31, kvh = h >> 2;
    const __half* qb = q  + ((size_t)b * SEQ + qt * 128) * HID + h * HD;
    const __half* kb = kk + (size_t)b * SEQ * (NKV * HD) + kvh * HD;
    const __half* vb = vv + (size_t)b * SEQ * (NKV * HD) + kvh * HD;

    int tid = threadIdx.x, warp = tid >> 5, lane = tid & 31;
    int wm = warp * 16;
    int g = lane >> 2, t = lane & 3;

    const __half2 sc8 = __floats2half2_rn(0.125f, 0.125f);   // exact power of two

    // load Q (128x64): 8 halves per thread-chunk, scaled
    #pragma unroll
    for (int i = 0; i < 4; i++) {
        int idx = tid + i * 256;                 // 1024 chunks of 8 halves
        int r = idx >> 3, c8 = idx & 7;
        const __half2* src = reinterpret_cast<const __half2*>(qb + (size_t)r * HID + c8 * 8);
        __half2* dst = reinterpret_cast<__half2*>(&Qs[r * APADH + c8 * 8]);
        dst[0] = __hmul2(src[0], sc8);
        dst[1] = __hmul2(src[1], sc8);
        dst[2] = __hmul2(src[2], sc8);
        dst[3] = __hmul2(src[3], sc8);
    }

    float acc_o[8][4] = {};
    float m_[2] = {-1e30f, -1e30f};
    float l_[2] = {0.f, 0.f};

    int ktmax = 2 * qt + 1;
    for (int kt = 0; kt <= ktmax; kt++) {
        // K rows raw 16B copies; V transposed scalar
        #pragma unroll
        for (int i = 0; i < 2; i++) {
            int idx = tid + i * 256;             // 512 chunks of 8 halves
            int r = idx >> 3, c8 = idx & 7;
            const float4 kv4 = *reinterpret_cast<const float4*>(kb + (size_t)(kt * 64 + r) * (NKV * HD) + c8 * 8);
            *reinterpret_cast<float4*>(&Ks[r * APADH + c8 * 8]) = kv4;
            const __half* vv8 = vb + (size_t)(kt * 64 + r) * (NKV * HD) + c8 * 8;
            #pragma unroll
            for (int e = 0; e < 8; e++)
                Vt[(c8 * 8 + e) * APADH + r] = vv8[e];
        }
        __syncthreads();

        // S = Qs @ Ks^T   (m16n8k16, 4 k-steps)
        float s[8][4] = {};
        #pragma unroll
        for (int ks = 0; ks < 64; ks += 16) {
            uint32_t a[4];
            int r = wm + g;
            a[0] = *reinterpret_cast<const uint32_t*>(&Qs[ r      * APADH + ks + 2*t]);
            a[1] = *reinterpret_cast<const uint32_t*>(&Qs[(r + 8) * APADH + ks + 2*t]);
            a[2] = *reinterpret_cast<const uint32_t*>(&Qs[ r      * APADH + ks + 2*t + 8]);
            a[3] = *reinterpret_cast<const uint32_t*>(&Qs[(r + 8) * APADH + ks + 2*t + 8]);
            #pragma unroll
            for (int ni = 0; ni < 8; ni++) {
                int c = ni * 8 + g;
                uint32_t b0 = *reinterpret_cast<const uint32_t*>(&Ks[c * APADH + ks + 2*t]);
                uint32_t b1 = *reinterpret_cast<const uint32_t*>(&Ks[c * APADH + ks + 2*t + 8]);
                asm volatile(
                    "mma.sync.aligned.m16n8k16.row.col.f32.f16.f16.f32 "
                    "{%0,%1,%2,%3},{%4,%5,%6,%7},{%8,%9},{%0,%1,%2,%3};"
                    : "+f"(s[ni][0]), "+f"(s[ni][1]), "+f"(s[ni][2]), "+f"(s[ni][3])
                    : "r"(a[0]), "r"(a[1]), "r"(a[2]), "r"(a[3]), "r"(b0), "r"(b1));
            }
        }

        if (kt >= 2 * qt) {
            int R0 = qt * 128 + wm + g, R1 = R0 + 8;
            #pragma unroll
            for (int ni = 0; ni < 8; ni++) {
                int c0 = kt * 64 + ni * 8 + 2 * t;
                if (c0     > R0) s[ni][0] = -1e30f;
                if (c0 + 1 > R0) s[ni][1] = -1e30f;
                if (c0     > R1) s[ni][2] = -1e30f;
                if (c0 + 1 > R1) s[ni][3] = -1e30f;
            }
        }

        #pragma unroll
        for (int rs = 0; rs < 2; rs++) {
            float mx = -1e30f;
            #pragma unroll
            for (int ni = 0; ni < 8; ni++)
                mx = fmaxf(mx, fmaxf(s[ni][rs*2], s[ni][rs*2+1]));
            mx = fmaxf(mx, __shfl_xor_sync(0xffffffffu, mx, 1));
            mx = fmaxf(mx, __shfl_xor_sync(0xffffffffu, mx, 2));
            float mnew = fmaxf(m_[rs], mx);
            float corr = __expf(m_[rs] - mnew);
            float ps = 0.f;
            #pragma unroll
            for (int ni = 0; ni < 8; ni++) {
                float p0 = __expf(s[ni][rs*2]     - mnew);
                float p1 = __expf(s[ni][rs*2 + 1] - mnew);
                s[ni][rs*2] = p0; s[ni][rs*2+1] = p1;
                ps += p0 + p1;
            }
            ps += __shfl_xor_sync(0xffffffffu, ps, 1);
            ps += __shfl_xor_sync(0xffffffffu, ps, 2);
            l_[rs] = l_[rs] * corr + ps;
            m_[rs] = mnew;
            #pragma unroll
            for (int ni = 0; ni < 8; ni++) {
                acc_o[ni][rs*2]   *= corr;
                acc_o[ni][rs*2+1] *= corr;
            }
        }

        // write P (fp16) to warp-private rows
        {
            int r0 = wm + g;
            #pragma unroll
            for (int ni = 0; ni < 8; ni++) {
                int c0 = ni * 8 + 2 * t;
                *reinterpret_cast<__half2*>(&Ps[ r0      * APADH + c0]) =
                    __floats2half2_rn(s[ni][0], s[ni][1]);
                *reinterpret_cast<__half2*>(&Ps[(r0 + 8) * APADH + c0]) =
                    __floats2half2_rn(s[ni][2], s[ni][3]);
            }
        }

        // O += P @ V
        #pragma unroll
        for (int ks = 0; ks < 64; ks += 16) {
            uint32_t a[4];
            int r = wm + g;
            a[0] = *reinterpret_cast<const uint32_t*>(&Ps[ r      * APADH + ks + 2*t]);
            a[1] = *reinterpret_cast<const uint32_t*>(&Ps[(r + 8) * APADH + ks + 2*t]);
            a[2] = *reinterpret_cast<const uint32_t*>(&Ps[ r      * APADH + ks + 2*t + 8]);
            a[3] = *reinterpret_cast<const uint32_t*>(&Ps[(r + 8) * APADH + ks + 2*t + 8]);
            #pragma unroll
            for (int ni = 0; ni < 8; ni++) {
                int c = ni * 8 + g;
                uint32_t b0 = *reinterpret_cast<const uint32_t*>(&Vt[c * APADH + ks + 2*t]);
                uint32_t b1 = *reinterpret_cast<const uint32_t*>(&Vt[c * APADH + ks + 2*t + 8]);
                asm volatile(
                    "mma.sync.aligned.m16n8k16.row.col.f32.f16.f16.f32 "
                    "{%0,%1,%2,%3},{%4,%5,%6,%7},{%8,%9},{%0,%1,%2,%3};"
                    : "+f"(acc_o[ni][0]), "+f"(acc_o[ni][1]),
                      "+f"(acc_o[ni][2]), "+f"(acc_o[ni][3])
                    : "r"(a[0]), "r"(a[1]), "r"(a[2]), "r"(a[3]), "r"(b0), "r"(b1));
            }
        }
        __syncthreads();
    }

    // epilogue: divide by l, fp16 ctx
    #pragma unroll
    for (int rs = 0; rs < 2; rs++) {
        float inv = 1.f / l_[rs];
        int r = qt * 128 + wm + rs * 8 + g;
        #pragma unroll
        for (int ni = 0; ni < 8; ni++) {
            int c = ni * 8 + 2 * t;
            *reinterpret_cast<__half2*>(ctx + (size_t)(b * SEQ + r) * HID + h * HD + c) =
                __floats2half2_rn(acc_o[ni][rs*2] * inv, acc_o[ni][rs*2+1] * inv);
        }
    }
}

// ---------------- driver ----------------
extern "C" void kernel_launch(void* const* d_in, const int* in_sizes, int n_in,
                              void* d_out, int out_size)
{
    const float* hidden  = (const float*)d_in[0];
    // d_in[1] = attention_mask (causal; applied analytically)
    const float* wq      = (const float*)d_in[2];
    const float* wk      = (const float*)d_in[3];
    const float* wv      = (const float*)d_in[4];
    const float* wo      = (const float*)d_in[5];
    const float* norm1w  = (const float*)d_in[6];
    const float* norm2w  = (const float*)d_in[7];
    const float* wgate   = (const float*)d_in[8];
    const float* wup     = (const float*)d_in[9];
    const float* wdown   = (const float*)d_in[10];
    const int*   posids  = (const int*)d_in[11];
    float* out = (float*)d_out;

    float *attn, *rope;
    __half *normed_h, *q_h, *k_h, *v_h, *ctx_h, *normed2_h, *u_h, *g_h;
    __half *wq_t, *wk_t, *wv_t, *wo_t, *wg_t, *wu_t, *wd_t;
    cudaGetSymbolAddress((void**)&attn,      d_attn);
    cudaGetSymbolAddress((void**)&rope,      d_rope);
    cudaGetSymbolAddress((void**)&normed_h,  d_normed_h);
    cudaGetSymbolAddress((void**)&q_h,       d_q_h);
    cudaGetSymbolAddress((void**)&k_h,       d_k_h);
    cudaGetSymbolAddress((void**)&v_h,       d_v_h);
    cudaGetSymbolAddress((void**)&ctx_h,     d_ctx_h);
    cudaGetSymbolAddress((void**)&normed2_h, d_normed2_h);
    cudaGetSymbolAddress((void**)&u_h,       d_u_h);
    cudaGetSymbolAddress((void**)&g_h,       d_g_h);
    cudaGetSymbolAddress((void**)&wq_t,      d_wq_t);
    cudaGetSymbolAddress((void**)&wk_t,      d_wk_t);
    cudaGetSymbolAddress((void**)&wv_t,      d_wv_t);
    cudaGetSymbolAddress((void**)&wo_t,      d_wo_t);
    cudaGetSymbolAddress((void**)&wg_t,      d_wg_t);
    cudaGetSymbolAddress((void**)&wu_t,      d_wu_t);
    cudaGetSymbolAddress((void**)&wd_t,      d_wd_t);

    cudaFuncSetAttribute(attn_mma, cudaFuncAttributeMaxDynamicSharedMemorySize, ATTM_SMEM);

    // 0) all weight transposes, ONE launch (59392 tiles)
    transpose_all<<<59392, 256>>>(wq, wk, wv, wo, wgate, wup, wdown,
                                  wq_t, wk_t, wv_t, wo_t, wg_t, wu_t, wd_t);
    // 1) pre-attention norm -> fp16
    rmsnorm_kernel<<<MROWS, 256>>>(hidden, nullptr, norm1w, normed_h);
    // 2) fused QKV (+ rope table) -> fp16 q/k/v
    qkv_kernel<<<dim3(24, 16), 256>>>(normed_h, wq_t, wk_t, wv_t, q_h, k_h, v_h, posids, rope);
    // 3) RoPE apply (in place, fp16)
    rope_apply<<<(MROWS * 40 * 32) / 256, 256>>>(q_h, k_h, rope);
    // 4) attention -> fp16 ctx
    attn_mma<<<dim3(8, 64), 256, ATTM_SMEM>>>(q_h, k_h, v_h, ctx_h);
    // 5) output projection (fp32 out: residual carrier)
    gemm_h<<<dim3(16, 16), 256>>>(ctx_h, wo_t, attn, nullptr, HID, HID, 0);
    // 6) post-attention norm (fused residual) -> fp16
    rmsnorm_kernel<<<MROWS, 256>>>(attn, hidden, norm2w, normed2_h);
    // 7) FFN: up + gate one launch (fp16 outs), then multiply in place
    upgate_kernel<<<dim3(128, 16), 256>>>(normed2_h, wu_t, wg_t, u_h, g_h);
    swiglu_mul<<<(MROWS * FFND / 2 + 255) / 256, 256>>>(g_h, u_h, MROWS * FFND / 2);
    // 8) down projection + final residual
    gemm_h<<<dim3(16, 16), 256>>>(g_h, wd_t, out, attn, HID, FFND, 1);
}